// round 11
// baseline (speedup 1.0000x reference)
#include <cuda_runtime.h>

#define BB 16
#define KK 512
#define DD 256
#define TT 4096
#define TTILE 128          // frames per block
#define DHALF 128          // d-rows per block (D split over grid.z)
#define NWARP 8
#define THREADS 256
#define DPW (DHALF / NWARP)  // 16 d-rows per warp
#define SPAN 64            // max block k-range staged
#define SPANP 80           // sPh row pitch: SPAN + WMAX zero-pad
#define WMAX 16            // max per-frame softmax window kept
#define WP 132             // sW row pitch (floats): 16B multiple + bank offset
#define THRESH 25.0f       // keep terms with weight ratio > e^-25

__global__ void __launch_bounds__(THREADS, 4) fused_upsample_kernel(
    const float* __restrict__ durations,  // (B, K)
    const float* __restrict__ phoneme,    // (B, D, K)
    const float* __restrict__ frame,      // (B, D, T)
    float* __restrict__ out)              // (B, D, T)
{
    extern __shared__ __align__(16) float sm[];
    float* sC  = sm;                              // KK centers
    float* sW  = sC + KK;                         // WMAX * WP   ([j][t] weights)
    float* sPh = sW + WMAX * WP;                  // DHALF * SPANP (also cumsum scratch)
    int* sKmn  = (int*)(sPh + DHALF * SPANP);     // TTILE
    int* sWid  = sKmn + TTILE;                    // TTILE
    int* sKb   = sWid + TTILE;                    // 2

    const int b     = blockIdx.y;
    const int t0    = blockIdx.x * TTILE;
    const int dbase = blockIdx.z * DHALF;
    const int tid   = threadIdx.x;
    const int lane  = tid & 31;
    const int warp  = tid >> 5;

    // ---- prologue: stage durations, EXACT sequential fp32 cumsum (thread 0) ----
    for (int i = tid; i < KK; i += THREADS) sPh[i] = durations[b * KK + i];
    if (tid == 0) { sKb[0] = KK; sKb[1] = 0; }
    for (int i = tid; i < WMAX * WP; i += THREADS) sW[i] = 0.0f;
    __syncthreads();
    if (tid == 0) {
        float s = 0.0f;
        #pragma unroll 8
        for (int k = 0; k < KK; ++k) {
            float dk = sPh[k];
            s += dk;                       // strictly sequential association
            sC[k] = s - 0.5f * dk;
        }
    }
    __syncthreads();

    // ---- phase 1: binary-search window + windowed softmax (1 thread / frame) ----
    if (tid < TTILE) {
        const int tt = tid;
        const float tc = (float)(t0 + tt) + 0.5f;
        int pos = 0;                       // count of centers < tc (ascending)
        #pragma unroll
        for (int step = 256; step; step >>= 1) {
            int np = pos + step;
            if (np <= KK && sC[np - 1] < tc) pos = np;
        }
        int ka = pos > 0 ? pos - 1 : 0;
        int kz = pos < KK ? pos : KK - 1;
        float da = fabsf(tc - sC[ka]);
        float db = fabsf(tc - sC[kz]);
        int kc; float dmin;
        if (da <= db) { kc = ka; dmin = da; } else { kc = kz; dmin = db; }
        const float m = -(dmin * dmin);    // max energy (dist^2 unimodal in k)
        const float nthr = m - THRESH;
        int kmn = kc, kmx = kc;
        while (kmn > 0) {                  // qualifying set is contiguous
            float df = tc - sC[kmn - 1];
            if (-(df * df) > nthr) --kmn; else break;
        }
        while (kmx < KK - 1) {
            float df = tc - sC[kmx + 1];
            if (-(df * df) > nthr) ++kmx; else break;
        }
        int wid = kmx - kmn + 1;
        if (wid > WMAX) wid = WMAX;
        float sum = 0.0f;
        for (int j = 0; j < wid; ++j) {
            float df = tc - sC[kmn + j];
            float x = __expf(-(df * df) - m);
            sW[j * WP + tt] = x;
            sum += x;
        }
        const float inv = 1.0f / sum;
        for (int j = 0; j < wid; ++j) sW[j * WP + tt] *= inv;
        sKmn[tt] = kmn;
        sWid[tt] = wid;
        atomicMin(&sKb[0], kmn);
        atomicMax(&sKb[1], kmx);
    }
    __syncthreads();

    const int kb = sKb[0];
    int span = sKb[1] - kb + 1;
    if (span > SPAN) span = SPAN;          // safety clamp (never triggers here)

    // ---- phase 2: bulk-stage the block's phoneme panel (coalesced, high MLP) ----
    for (int r = warp; r < DHALF; r += NWARP) {
        const float* prow = phoneme + ((size_t)b * DD + dbase + r) * KK + kb;
        int c0 = lane, c1 = lane + 32;
        float* dst = sPh + r * SPANP;
        dst[c0] = (c0 < span) ? prow[c0] : 0.0f;
        dst[c1] = (c1 < span) ? prow[c1] : 0.0f;
        if (lane < SPANP - SPAN) dst[SPAN + lane] = 0.0f;   // pad tail
    }
    __syncthreads();

    // ---- phase 3: i-unroll x2 (weights shared across 2 d-rows), fixed j-unroll 8 ----
    const int tbase = 4 * lane;
    const int q0 = min(sKmn[tbase + 0] - kb, SPAN - 1);
    const int q1 = min(sKmn[tbase + 1] - kb, SPAN - 1);
    const int q2 = min(sKmn[tbase + 2] - kb, SPAN - 1);
    const int q3 = min(sKmn[tbase + 3] - kb, SPAN - 1);
    const int wm = max(max(sWid[tbase], sWid[tbase + 1]),
                       max(sWid[tbase + 2], sWid[tbase + 3]));
    const bool wide = wm > 8;              // warp-uniform (same 4 t's for all lanesets? no —
                                           // per-lane t's differ, but branch is per-thread-safe;
                                           // divergence cost only when rare windows straddle)

    const int dw = warp * DPW;
    const size_t fo = ((size_t)b * DD + dbase) * TT + t0 + tbase;
    const float* frp = frame + fo;
    float* op = out + fo;

    // frame prefetch: pair-wise, 2-4 LDG.128 in flight
    float4 fA = *(const float4*)(frp + (size_t)dw * TT);
    float4 fB = *(const float4*)(frp + (size_t)(dw + 1) * TT);

    #pragma unroll 1
    for (int i = 0; i < DPW; i += 2) {
        const float* pr0 = sPh + (dw + i) * SPANP;
        const float* pr1 = pr0 + SPANP;
        float4 f0 = fA, f1 = fB;
        if (i + 2 < DPW) {
            fA = *(const float4*)(frp + (size_t)(dw + i + 2) * TT);
            fB = *(const float4*)(frp + (size_t)(dw + i + 3) * TT);
        }

        float ax0 = 0.f, ay0 = 0.f, az0 = 0.f, aw0 = 0.f;
        float ax1 = 0.f, ay1 = 0.f, az1 = 0.f, aw1 = 0.f;
        #pragma unroll
        for (int j = 0; j < 8; ++j) {      // weights zero-padded: exact no-op past wid
            float4 w4 = *(const float4*)(sW + j * WP + tbase);
            ax0 = fmaf(w4.x, pr0[q0 + j], ax0);
            ay0 = fmaf(w4.y, pr0[q1 + j], ay0);
            az0 = fmaf(w4.z, pr0[q2 + j], az0);
            aw0 = fmaf(w4.w, pr0[q3 + j], aw0);
            ax1 = fmaf(w4.x, pr1[q0 + j], ax1);
            ay1 = fmaf(w4.y, pr1[q1 + j], ay1);
            az1 = fmaf(w4.z, pr1[q2 + j], az1);
            aw1 = fmaf(w4.w, pr1[q3 + j], aw1);
        }
        if (wide) {                        // rare wide windows: identical tail semantics
            for (int j = 8; j < wm; ++j) {
                float4 w4 = *(const float4*)(sW + j * WP + tbase);
                ax0 = fmaf(w4.x, pr0[q0 + j], ax0);
                ay0 = fmaf(w4.y, pr0[q1 + j], ay0);
                az0 = fmaf(w4.z, pr0[q2 + j], az0);
                aw0 = fmaf(w4.w, pr0[q3 + j], aw0);
                ax1 = fmaf(w4.x, pr1[q0 + j], ax1);
                ay1 = fmaf(w4.y, pr1[q1 + j], ay1);
                az1 = fmaf(w4.z, pr1[q2 + j], az1);
                aw1 = fmaf(w4.w, pr1[q3 + j], aw1);
            }
        }
        *(float4*)(op + (size_t)(dw + i) * TT) =
            make_float4(f0.x + ax0, f0.y + ay0, f0.z + az0, f0.w + aw0);
        *(float4*)(op + (size_t)(dw + i + 1) * TT) =
            make_float4(f1.x + ax1, f1.y + ay1, f1.z + az1, f1.w + aw1);
    }
}

extern "C" void kernel_launch(void* const* d_in, const int* in_sizes, int n_in,
                              void* d_out, int out_size) {
    const float* durations = (const float*)d_in[0];  // (B, K)
    const float* phoneme   = (const float*)d_in[1];  // (B, D, K)
    const float* frame     = (const float*)d_in[2];  // (B, D, T)
    float* out = (float*)d_out;                      // (B, D, T)

    size_t smem = (size_t)(KK + WMAX * WP + DHALF * SPANP) * sizeof(float)
                + (size_t)(2 * TTILE + 2) * sizeof(int);
    cudaFuncSetAttribute(fused_upsample_kernel,
                         cudaFuncAttributeMaxDynamicSharedMemorySize, (int)smem);
    dim3 grid(TT / TTILE, BB, DD / DHALF);
    fused_upsample_kernel<<<grid, THREADS, smem>>>(durations, phoneme, frame, out);
}

// round 12
// speedup vs baseline: 1.3551x; 1.3551x over previous
#include <cuda_runtime.h>

#define BB 16
#define KK 512
#define DD 256
#define TT 4096
#define TTILE 128          // frames per block
#define DHALF 128          // d-rows per block (D split over grid.z)
#define NWARP 8
#define THREADS 256
#define DPW (DHALF / NWARP)  // 16 d-rows per warp
#define SPAN 64            // max block k-range staged
#define SPANP 80           // sPh row pitch: SPAN + WMAX zero-pad
#define WMAX 16            // max per-frame softmax window kept
#define WP 132             // sW row pitch (floats): 16B multiple + bank offset
#define THRESH 25.0f       // keep terms with weight ratio > e^-25

__global__ void __launch_bounds__(THREADS, 4) fused_upsample_kernel(
    const float* __restrict__ durations,  // (B, K)
    const float* __restrict__ phoneme,    // (B, D, K)
    const float* __restrict__ frame,      // (B, D, T)
    float* __restrict__ out)              // (B, D, T)
{
    extern __shared__ __align__(16) float sm[];
    float* sC  = sm;                              // KK centers
    float* sW  = sC + KK;                         // WMAX * WP   ([j][t] weights)
    float* sPh = sW + WMAX * WP;                  // DHALF * SPANP (also cumsum scratch)
    int* sKmn  = (int*)(sPh + DHALF * SPANP);     // TTILE
    int* sWid  = sKmn + TTILE;                    // TTILE
    int* sKb   = sWid + TTILE;                    // 2

    const int b     = blockIdx.y;
    const int t0    = blockIdx.x * TTILE;
    const int dbase = blockIdx.z * DHALF;
    const int tid   = threadIdx.x;
    const int lane  = tid & 31;
    const int warp  = tid >> 5;

    // ---- prologue: stage durations, EXACT sequential fp32 cumsum (thread 0) ----
    for (int i = tid; i < KK; i += THREADS) sPh[i] = durations[b * KK + i];
    if (tid == 0) { sKb[0] = KK; sKb[1] = 0; }
    for (int i = tid; i < WMAX * WP; i += THREADS) sW[i] = 0.0f;
    __syncthreads();
    if (tid == 0) {
        float s = 0.0f;
        #pragma unroll 8
        for (int k = 0; k < KK; ++k) {
            float dk = sPh[k];
            s += dk;                       // strictly sequential association
            sC[k] = s - 0.5f * dk;
        }
    }
    __syncthreads();

    // ---- phase 1: binary-search window + windowed softmax (1 thread / frame) ----
    if (tid < TTILE) {
        const int tt = tid;
        const float tc = (float)(t0 + tt) + 0.5f;
        int pos = 0;                       // count of centers < tc (ascending)
        #pragma unroll
        for (int step = 256; step; step >>= 1) {
            int np = pos + step;
            if (np <= KK && sC[np - 1] < tc) pos = np;
        }
        int ka = pos > 0 ? pos - 1 : 0;
        int kz = pos < KK ? pos : KK - 1;
        float da = fabsf(tc - sC[ka]);
        float db = fabsf(tc - sC[kz]);
        int kc; float dmin;
        if (da <= db) { kc = ka; dmin = da; } else { kc = kz; dmin = db; }
        const float m = -(dmin * dmin);    // max energy (dist^2 unimodal in k)
        const float nthr = m - THRESH;
        int kmn = kc, kmx = kc;
        while (kmn > 0) {                  // qualifying set is contiguous
            float df = tc - sC[kmn - 1];
            if (-(df * df) > nthr) --kmn; else break;
        }
        while (kmx < KK - 1) {
            float df = tc - sC[kmx + 1];
            if (-(df * df) > nthr) ++kmx; else break;
        }
        int wid = kmx - kmn + 1;
        if (wid > WMAX) wid = WMAX;
        float sum = 0.0f;
        for (int j = 0; j < wid; ++j) {
            float df = tc - sC[kmn + j];
            float x = __expf(-(df * df) - m);
            sW[j * WP + tt] = x;
            sum += x;
        }
        const float inv = 1.0f / sum;
        for (int j = 0; j < wid; ++j) sW[j * WP + tt] *= inv;
        sKmn[tt] = kmn;
        sWid[tt] = wid;
        atomicMin(&sKb[0], kmn);
        atomicMax(&sKb[1], kmx);
    }
    __syncthreads();

    const int kb = sKb[0];
    int span = sKb[1] - kb + 1;
    if (span > SPAN) span = SPAN;          // safety clamp (never triggers here)

    // ---- phase 2: bulk-stage the block's phoneme panel (coalesced, high MLP) ----
    for (int r = warp; r < DHALF; r += NWARP) {
        const float* prow = phoneme + ((size_t)b * DD + dbase + r) * KK + kb;
        int c0 = lane, c1 = lane + 32;
        float* dst = sPh + r * SPANP;
        dst[c0] = (c0 < span) ? prow[c0] : 0.0f;
        dst[c1] = (c1 < span) ? prow[c1] : 0.0f;
        if (lane < SPANP - SPAN) dst[SPAN + lane] = 0.0f;   // pad tail
    }
    __syncthreads();

    // ---- phase 3: R10 body + i-unroll x2, runtime j-loop (one w4 feeds 2 d-rows) ----
    const int tbase = 4 * lane;
    const int q0 = min(sKmn[tbase + 0] - kb, SPAN - 1);
    const int q1 = min(sKmn[tbase + 1] - kb, SPAN - 1);
    const int q2 = min(sKmn[tbase + 2] - kb, SPAN - 1);
    const int q3 = min(sKmn[tbase + 3] - kb, SPAN - 1);
    const int wm = max(max(sWid[tbase], sWid[tbase + 1]),
                       max(sWid[tbase + 2], sWid[tbase + 3]));

    const int dw = warp * DPW;
    const size_t fo = ((size_t)b * DD + dbase) * TT + t0 + tbase;
    const float* frp = frame + fo;
    float* op = out + fo;

    // depth-2 (pair) frame prefetch
    float4 fA = *(const float4*)(frp + (size_t)dw * TT);
    float4 fB = *(const float4*)(frp + (size_t)(dw + 1) * TT);

    #pragma unroll 1
    for (int i = 0; i < DPW; i += 2) {
        const float* pr0 = sPh + (dw + i) * SPANP;
        const float* pr1 = pr0 + SPANP;
        float4 f0 = fA, f1 = fB;
        if (i + 2 < DPW) {
            fA = *(const float4*)(frp + (size_t)(dw + i + 2) * TT);
            fB = *(const float4*)(frp + (size_t)(dw + i + 3) * TT);
        }

        float ax0 = 0.f, ay0 = 0.f, az0 = 0.f, aw0 = 0.f;
        float ax1 = 0.f, ay1 = 0.f, az1 = 0.f, aw1 = 0.f;
        #pragma unroll 1
        for (int j = 0; j < wm; ++j) {     // adaptive trip count (typ. 2-4)
            float4 w4 = *(const float4*)(sW + j * WP + tbase);
            ax0 = fmaf(w4.x, pr0[q0 + j], ax0);
            ay0 = fmaf(w4.y, pr0[q1 + j], ay0);
            az0 = fmaf(w4.z, pr0[q2 + j], az0);
            aw0 = fmaf(w4.w, pr0[q3 + j], aw0);
            ax1 = fmaf(w4.x, pr1[q0 + j], ax1);
            ay1 = fmaf(w4.y, pr1[q1 + j], ay1);
            az1 = fmaf(w4.z, pr1[q2 + j], az1);
            aw1 = fmaf(w4.w, pr1[q3 + j], aw1);
        }
        *(float4*)(op + (size_t)(dw + i) * TT) =
            make_float4(f0.x + ax0, f0.y + ay0, f0.z + az0, f0.w + aw0);
        *(float4*)(op + (size_t)(dw + i + 1) * TT) =
            make_float4(f1.x + ax1, f1.y + ay1, f1.z + az1, f1.w + aw1);
    }
}

extern "C" void kernel_launch(void* const* d_in, const int* in_sizes, int n_in,
                              void* d_out, int out_size) {
    const float* durations = (const float*)d_in[0];  // (B, K)
    const float* phoneme   = (const float*)d_in[1];  // (B, D, K)
    const float* frame     = (const float*)d_in[2];  // (B, D, T)
    float* out = (float*)d_out;                      // (B, D, T)

    size_t smem = (size_t)(KK + WMAX * WP + DHALF * SPANP) * sizeof(float)
                + (size_t)(2 * TTILE + 2) * sizeof(int);
    cudaFuncSetAttribute(fused_upsample_kernel,
                         cudaFuncAttributeMaxDynamicSharedMemorySize, (int)smem);
    dim3 grid(TT / TTILE, BB, DD / DHALF);
    fused_upsample_kernel<<<grid, THREADS, smem>>>(durations, phoneme, frame, out);
}